// round 13
// baseline (speedup 1.0000x reference)
#include <cuda_runtime.h>
#include <cuda.h>
#include <math.h>

#define Hh 512
#define Ww 512
#define Ss 5
#define Cin 2
#define Cout 2

#define TW 128
#define TH 16
#define ROWS (TH + 2)     // 18
#define NPLANES 10
#define RSTRIDE 136       // smem col i <-> global col w_base-4+i
#define PLANE (ROWS * RSTRIDE)                  // 2448 floats
#define CHUNK_BYTES (2 * PLANE * 4)             // 19584 (2 planes per timestep)
#define TILE_BYTES (NPLANES * PLANE * 4)        // 97920
#define TILE_OFF 1024
#define SMEM_BYTES (TILE_OFF + TILE_BYTES)      // 98944

extern __shared__ __align__(1024) char smem_arena[];

__device__ __forceinline__ void mbar_wait(unsigned int addr) {
    unsigned int done;
    asm volatile(
        "{\n\t.reg .pred p;\n\t"
        "mbarrier.try_wait.parity.acquire.cta.shared::cta.b64 p, [%1], 0;\n\t"
        "selp.b32 %0, 1, 0, p;\n\t}"
        : "=r"(done) : "r"(addr) : "memory");
    if (!done) {
        asm volatile(
            "{\n\t.reg .pred P1;\n\t"
            "WL_%=:\n\t"
            "mbarrier.try_wait.parity.acquire.cta.shared::cta.b64 P1, [%0], 0, 0x989680;\n\t"
            "@P1 bra.uni WD_%=;\n\t"
            "bra.uni WL_%=;\n\t"
            "WD_%=:\n\t}"
            :: "r"(addr) : "memory");
    }
}

__global__ __launch_bounds__(512, 2)
void snn_fused11(const __grid_constant__ CUtensorMap tmap,
                 const float* __restrict__ conv_w,
                 const float* __restrict__ conv_b,
                 const float* __restrict__ gamma,
                 const float* __restrict__ beta_bn,
                 const float* __restrict__ run_mean,
                 const float* __restrict__ run_var,
                 const float* __restrict__ rho,
                 float* __restrict__ out)
{
    // arena: [0,40) mbar[5] ; [64,208) sw ; [208,216) sb ; [216,224) sad ; [1024,..) tile
    unsigned long long* mbar = (unsigned long long*)smem_arena;
    float* sw  = (float*)(smem_arena + 64);
    float* sb  = (float*)(smem_arena + 208);
    float* sad = (float*)(smem_arena + 216);
    float* tile = (float*)(smem_arena + TILE_OFF);

    const int tx  = threadIdx.x;          // 0..31
    const int ty  = threadIdx.y;          // 0..15
    const int tid = ty * 32 + tx;
    const int b      = blockIdx.z;
    const int h_base = blockIdx.y * TH;
    const int w_base = blockIdx.x * TW;

    unsigned int mbar_a, tile_a;
    asm("{ .reg .u64 t; cvta.to.shared.u64 t, %1; cvt.u32.u64 %0, t; }"
        : "=r"(mbar_a) : "l"(mbar));
    asm("{ .reg .u64 t; cvta.to.shared.u64 t, %1; cvt.u32.u64 %0, t; }"
        : "=r"(tile_a) : "l"(tile));

    if (tid < Ss) {
        asm volatile("mbarrier.init.shared.b64 [%0], 1;"
                     :: "r"(mbar_a + tid * 8) : "memory");
    }
    if (tid >= 32 && tid < 32 + Cout * Cin * 9) {
        int i = tid - 32;
        int o = i / (Cin * 9);
        sw[i] = conv_w[i] * (gamma[o] * rsqrtf(run_var[o] + 1e-5f));
    }
    if (tid >= 96 && tid < 96 + Cout) {
        int o = tid - 96;
        float inv = gamma[o] * rsqrtf(run_var[o] + 1e-5f);
        sb[o]  = (conv_b[o] - run_mean[o]) * inv + beta_bn[o];
        float rc = fminf(fmaxf(rho[o], 0.032f), 0.055f);
        sad[o] = expf(-0.05f / rc);
    }
    __syncthreads();   // mbar init + weights visible

    // ---- 5 chunked TMAs (2 planes each), issued concurrently by threads 0..4 ----
    if (tid < Ss) {
        unsigned int mb = mbar_a + tid * 8;
        asm volatile("mbarrier.arrive.expect_tx.shared.b64 _, [%0], %1;"
                     :: "r"(mb), "r"((unsigned)CHUNK_BYTES) : "memory");
        int cx = w_base - 4;
        int cy = h_base - 1;
        int cz = b * NPLANES + tid * 2;
        unsigned int dst = tile_a + (unsigned)(tid * 2 * PLANE * 4);
        asm volatile(
            "cp.async.bulk.tensor.3d.shared::cta.global.tile.mbarrier::complete_tx::bytes "
            "[%0], [%1, {%2, %3, %4}], [%5];"
            :: "r"(dst), "l"(&tmap), "r"(cx), "r"(cy), "r"(cz), "r"(mb)
            : "memory");
    }

    const size_t img = (size_t)Hh * Ww;
    const int P = 4 * tx;
    const int h0 = h_base + ty;
    const size_t opix = (size_t)h0 * Ww + w_base + P;

    float mem[Cout][4], aa[Cout][4];
    #pragma unroll
    for (int o = 0; o < Cout; o++)
        #pragma unroll
        for (int k = 0; k < 4; k++) { mem[o][k] = 0.f; aa[o][k] = 0.f; }

    #pragma unroll
    for (int s = 0; s < Ss; s++) {
        mbar_wait(mbar_a + s * 8);     // chunk s ready; later chunks still in flight

        float acc[Cout][4];
        #pragma unroll
        for (int o = 0; o < Cout; o++)
            #pragma unroll
            for (int k = 0; k < 4; k++) acc[o][k] = 0.f;

        #pragma unroll
        for (int c = 0; c < Cin; c++) {
            const int p = s * 2 + c;
            const float* pl = &tile[p * PLANE + ty * RSTRIDE];
            #pragma unroll
            for (int r = 0; r < 3; r++) {
                const float* rp = pl + r * RSTRIDE;
                float4 B4 = *(const float4*)(rp + 4 + P);             // cols P+4..P+7
                float left  = __shfl_up_sync(0xffffffffu, B4.w, 1);   // col P+3
                float right = __shfl_down_sync(0xffffffffu, B4.x, 1); // col P+8
                if (tx == 0)  left  = rp[3];
                if (tx == 31) right = rp[132];
                float vv0 = left, vv1 = B4.x, vv2 = B4.y,
                      vv3 = B4.z, vv4 = B4.w, vv5 = right;
                #pragma unroll
                for (int o = 0; o < Cout; o++) {
                    const float* w = &sw[(o * Cin + c) * 9 + r * 3];
                    float w0 = w[0], w1 = w[1], w2 = w[2];
                    float a0 = acc[o][0], a1 = acc[o][1], a2 = acc[o][2], a3 = acc[o][3];
                    a0 = fmaf(vv0, w0, a0); a0 = fmaf(vv1, w1, a0); a0 = fmaf(vv2, w2, a0);
                    a1 = fmaf(vv1, w0, a1); a1 = fmaf(vv2, w1, a1); a1 = fmaf(vv3, w2, a1);
                    a2 = fmaf(vv2, w0, a2); a2 = fmaf(vv3, w1, a2); a2 = fmaf(vv4, w2, a2);
                    a3 = fmaf(vv3, w0, a3); a3 = fmaf(vv4, w1, a3); a3 = fmaf(vv5, w2, a3);
                    acc[o][0] = a0; acc[o][1] = a1; acc[o][2] = a2; acc[o][3] = a3;
                }
            }
        }

        #pragma unroll
        for (int o = 0; o < Cout; o++) {
            const float bias = sb[o];
            const float ad   = sad[o];
            float spk[4];
            #pragma unroll
            for (int k = 0; k < 4; k++) {
                float Ath = 0.3f + 0.07f * aa[o][k];
                float m = mem[o][k] + acc[o][k] + bias;
                float sv = (m > Ath) ? 1.f : 0.f;
                mem[o][k] = m * 0.2f * (1.f - sv);
                aa[o][k] = ad * aa[o][k] + sv;
                spk[k] = sv;
            }
            float4 v4 = make_float4(spk[0], spk[1], spk[2], spk[3]);
            __stcs((float4*)(out + ((size_t)(b * 10 + s * 2 + o)) * img + opix), v4);
        }
    }
}

typedef CUresult (CUDAAPI *PFN_encodeTiled_local)(
    CUtensorMap*, CUtensorMapDataType, cuuint32_t, void*,
    const cuuint64_t*, const cuuint64_t*, const cuuint32_t*, const cuuint32_t*,
    CUtensorMapInterleave, CUtensorMapSwizzle, CUtensorMapL2promotion,
    CUtensorMapFloatOOBfill);

extern "C" void kernel_launch(void* const* d_in, const int* in_sizes, int n_in,
                              void* d_out, int out_size)
{
    const float* all_input = (const float*)d_in[0];
    const float* conv_w    = (const float*)d_in[1];
    const float* conv_b    = (const float*)d_in[2];
    const float* gamma     = (const float*)d_in[3];
    const float* beta_bn   = (const float*)d_in[4];
    const float* run_mean  = (const float*)d_in[5];
    const float* run_var   = (const float*)d_in[6];
    const float* rho       = (const float*)d_in[7];
    float* out = (float*)d_out;

    PFN_encodeTiled_local encode = nullptr;
    cudaDriverEntryPointQueryResult qr;
    cudaGetDriverEntryPoint("cuTensorMapEncodeTiled", (void**)&encode,
                            cudaEnableDefault, &qr);

    CUtensorMap tmap;
    {
        cuuint64_t dims[3]    = { (cuuint64_t)Ww, (cuuint64_t)Hh,
                                  (cuuint64_t)(16 * NPLANES) };
        cuuint64_t strides[2] = { (cuuint64_t)Ww * 4,
                                  (cuuint64_t)Hh * Ww * 4 };
        cuuint32_t box[3]     = { (cuuint32_t)RSTRIDE, (cuuint32_t)ROWS, 2 };
        cuuint32_t estr[3]    = { 1, 1, 1 };
        encode(&tmap, CU_TENSOR_MAP_DATA_TYPE_FLOAT32, 3, (void*)all_input,
               dims, strides, box, estr,
               CU_TENSOR_MAP_INTERLEAVE_NONE, CU_TENSOR_MAP_SWIZZLE_NONE,
               CU_TENSOR_MAP_L2_PROMOTION_L2_128B,
               CU_TENSOR_MAP_FLOAT_OOB_FILL_NONE);
    }

    cudaFuncSetAttribute(snn_fused11,
                         cudaFuncAttributeMaxDynamicSharedMemorySize, SMEM_BYTES);

    dim3 block(32, TH, 1);                 // 512 threads
    dim3 grid(Ww / TW, Hh / TH, 16);       // 2048 blocks
    snn_fused11<<<grid, block, SMEM_BYTES>>>(tmap, conv_w, conv_b, gamma, beta_bn,
                                             run_mean, run_var, rho, out);
}

// round 16
// speedup vs baseline: 1.6490x; 1.6490x over previous
#include <cuda_runtime.h>
#include <cuda.h>
#include <math.h>

#define Hh 512
#define Ww 512
#define Ss 5
#define Cin 2
#define Cout 2

#define TW 128
#define TH 8
#define ROWS (TH + 2)     // 10
#define NPLANES 10
#define RSTRIDE 136       // smem col i <-> global col w_base-4+i ; interior 4..131, halos 3 / 132
#define PLANE (ROWS * RSTRIDE)                  // 1360 floats
#define TILE_BYTES (NPLANES * PLANE * 4)        // 54400
#define TILE_OFF 1024
#define SMEM_BYTES (TILE_OFF + TILE_BYTES)      // 55424

extern __shared__ __align__(1024) char smem_arena[];

__global__ __launch_bounds__(256, 4)
void snn_fused14(const __grid_constant__ CUtensorMap tmap,
                 const float* __restrict__ conv_w,
                 const float* __restrict__ conv_b,
                 const float* __restrict__ gamma,
                 const float* __restrict__ beta_bn,
                 const float* __restrict__ run_mean,
                 const float* __restrict__ run_var,
                 const float* __restrict__ rho,
                 float* __restrict__ out)
{
    // arena: [0,8) mbar ; [64,208) sw ; [208,216) sb ; [216,224) sad ; [1024,..) tile
    unsigned long long* mbar = (unsigned long long*)smem_arena;
    float* sw  = (float*)(smem_arena + 64);
    float* sb  = (float*)(smem_arena + 208);
    float* sad = (float*)(smem_arena + 216);
    float* tile = (float*)(smem_arena + TILE_OFF);

    const int tx  = threadIdx.x;          // 0..31
    const int ty  = threadIdx.y;          // 0..7
    const int tid = ty * 32 + tx;
    const int b      = blockIdx.z;
    const int h_base = blockIdx.y * TH;
    const int w_base = blockIdx.x * TW;

    unsigned int mbar_a, tile_a;
    asm("{ .reg .u64 t; cvta.to.shared.u64 t, %1; cvt.u32.u64 %0, t; }"
        : "=r"(mbar_a) : "l"(mbar));
    asm("{ .reg .u64 t; cvta.to.shared.u64 t, %1; cvt.u32.u64 %0, t; }"
        : "=r"(tile_a) : "l"(tile));

    if (tid == 0) {
        asm volatile("mbarrier.init.shared.b64 [%0], 1;" :: "r"(mbar_a) : "memory");
    }
    if (tid >= 32 && tid < 32 + Cout * Cin * 9) {
        int i = tid - 32;
        int o = i / (Cin * 9);
        sw[i] = conv_w[i] * (gamma[o] * rsqrtf(run_var[o] + 1e-5f));
    }
    if (tid >= 96 && tid < 96 + Cout) {
        int o = tid - 96;
        float inv = gamma[o] * rsqrtf(run_var[o] + 1e-5f);
        sb[o]  = (conv_b[o] - run_mean[o]) * inv + beta_bn[o];
        float rc = fminf(fmaxf(rho[o], 0.032f), 0.055f);
        sad[o] = expf(-0.05f / rc);
    }
    __syncthreads();   // mbar init + weights visible

    // ---- one bulk TMA: box (136 x 10 x 10) f32, OOB zero-filled ----
    if (tid == 0) {
        asm volatile("mbarrier.arrive.expect_tx.shared.b64 _, [%0], %1;"
                     :: "r"(mbar_a), "r"((unsigned)TILE_BYTES) : "memory");
        int cx = w_base - 4;
        int cy = h_base - 1;
        int cz = b * NPLANES;
        asm volatile(
            "cp.async.bulk.tensor.3d.shared::cta.global.tile.mbarrier::complete_tx::bytes "
            "[%0], [%1, {%2, %3, %4}], [%5];"
            :: "r"(tile_a), "l"(&tmap), "r"(cx), "r"(cy), "r"(cz), "r"(mbar_a)
            : "memory");
    }
    {
        unsigned int done;
        asm volatile(
            "{\n\t.reg .pred p;\n\t"
            "mbarrier.try_wait.parity.acquire.cta.shared::cta.b64 p, [%1], 0;\n\t"
            "selp.b32 %0, 1, 0, p;\n\t}"
            : "=r"(done) : "r"(mbar_a) : "memory");
        if (!done) {
            asm volatile(
                "{\n\t.reg .pred P1;\n\t"
                "WL_%=:\n\t"
                "mbarrier.try_wait.parity.acquire.cta.shared::cta.b64 P1, [%0], 0, 0x989680;\n\t"
                "@P1 bra.uni WD_%=;\n\t"
                "bra.uni WL_%=;\n\t"
                "WD_%=:\n\t}"
                :: "r"(mbar_a) : "memory");
        }
    }

    const size_t img = (size_t)Hh * Ww;
    const int P = 4 * tx;
    const int h0 = h_base + ty;
    const size_t opix = (size_t)h0 * Ww + w_base + P;

    float mem[Cout][4], aa[Cout][4];
    #pragma unroll
    for (int o = 0; o < Cout; o++)
        #pragma unroll
        for (int k = 0; k < 4; k++) { mem[o][k] = 0.f; aa[o][k] = 0.f; }

    #pragma unroll
    for (int s = 0; s < Ss; s++) {
        float acc[Cout][4];
        #pragma unroll
        for (int o = 0; o < Cout; o++)
            #pragma unroll
            for (int k = 0; k < 4; k++) acc[o][k] = 0.f;

        #pragma unroll
        for (int c = 0; c < Cin; c++) {
            const int p = s * 2 + c;
            const float* pl = &tile[p * PLANE + ty * RSTRIDE];
            #pragma unroll
            for (int r = 0; r < 3; r++) {
                const float* rp = pl + r * RSTRIDE;
                float4 B4 = *(const float4*)(rp + 4 + P);             // cols P+4..P+7
                float left  = __shfl_up_sync(0xffffffffu, B4.w, 1);   // col P+3
                float right = __shfl_down_sync(0xffffffffu, B4.x, 1); // col P+8
                if (tx == 0)  left  = rp[3];
                if (tx == 31) right = rp[132];
                float vv0 = left, vv1 = B4.x, vv2 = B4.y,
                      vv3 = B4.z, vv4 = B4.w, vv5 = right;
                #pragma unroll
                for (int o = 0; o < Cout; o++) {
                    const float* w = &sw[(o * Cin + c) * 9 + r * 3];
                    float w0 = w[0], w1 = w[1], w2 = w[2];
                    float a0 = acc[o][0], a1 = acc[o][1], a2 = acc[o][2], a3 = acc[o][3];
                    a0 = fmaf(vv0, w0, a0); a0 = fmaf(vv1, w1, a0); a0 = fmaf(vv2, w2, a0);
                    a1 = fmaf(vv1, w0, a1); a1 = fmaf(vv2, w1, a1); a1 = fmaf(vv3, w2, a1);
                    a2 = fmaf(vv2, w0, a2); a2 = fmaf(vv3, w1, a2); a2 = fmaf(vv4, w2, a2);
                    a3 = fmaf(vv3, w0, a3); a3 = fmaf(vv4, w1, a3); a3 = fmaf(vv5, w2, a3);
                    acc[o][0] = a0; acc[o][1] = a1; acc[o][2] = a2; acc[o][3] = a3;
                }
            }
        }

        #pragma unroll
        for (int o = 0; o < Cout; o++) {
            const float bias = sb[o];
            const float ad   = sad[o];
            float spk[4];
            #pragma unroll
            for (int k = 0; k < 4; k++) {
                float Ath = 0.3f + 0.07f * aa[o][k];
                float m = mem[o][k] + acc[o][k] + bias;
                float sv = (m > Ath) ? 1.f : 0.f;
                mem[o][k] = m * 0.2f * (1.f - sv);
                aa[o][k] = ad * aa[o][k] + sv;
                spk[k] = sv;
            }
            float4 v4 = make_float4(spk[0], spk[1], spk[2], spk[3]);
            __stcs((float4*)(out + ((size_t)(b * 10 + s * 2 + o)) * img + opix), v4);
        }
    }
}

typedef CUresult (CUDAAPI *PFN_encodeTiled_local)(
    CUtensorMap*, CUtensorMapDataType, cuuint32_t, void*,
    const cuuint64_t*, const cuuint64_t*, const cuuint32_t*, const cuuint32_t*,
    CUtensorMapInterleave, CUtensorMapSwizzle, CUtensorMapL2promotion,
    CUtensorMapFloatOOBfill);

extern "C" void kernel_launch(void* const* d_in, const int* in_sizes, int n_in,
                              void* d_out, int out_size)
{
    const float* all_input = (const float*)d_in[0];
    const float* conv_w    = (const float*)d_in[1];
    const float* conv_b    = (const float*)d_in[2];
    const float* gamma     = (const float*)d_in[3];
    const float* beta_bn   = (const float*)d_in[4];
    const float* run_mean  = (const float*)d_in[5];
    const float* run_var   = (const float*)d_in[6];
    const float* rho       = (const float*)d_in[7];
    float* out = (float*)d_out;

    PFN_encodeTiled_local encode = nullptr;
    cudaDriverEntryPointQueryResult qr;
    cudaGetDriverEntryPoint("cuTensorMapEncodeTiled", (void**)&encode,
                            cudaEnableDefault, &qr);

    CUtensorMap tmap;
    {
        cuuint64_t dims[3]    = { (cuuint64_t)Ww, (cuuint64_t)Hh,
                                  (cuuint64_t)(16 * NPLANES) };
        cuuint64_t strides[2] = { (cuuint64_t)Ww * 4,
                                  (cuuint64_t)Hh * Ww * 4 };
        cuuint32_t box[3]     = { (cuuint32_t)RSTRIDE, (cuuint32_t)ROWS,
                                  (cuuint32_t)NPLANES };
        cuuint32_t estr[3]    = { 1, 1, 1 };
        encode(&tmap, CU_TENSOR_MAP_DATA_TYPE_FLOAT32, 3, (void*)all_input,
               dims, strides, box, estr,
               CU_TENSOR_MAP_INTERLEAVE_NONE, CU_TENSOR_MAP_SWIZZLE_NONE,
               CU_TENSOR_MAP_L2_PROMOTION_L2_128B,
               CU_TENSOR_MAP_FLOAT_OOB_FILL_NONE);
    }

    cudaFuncSetAttribute(snn_fused14,
                         cudaFuncAttributeMaxDynamicSharedMemorySize, SMEM_BYTES);

    dim3 block(32, TH, 1);                 // 256 threads
    dim3 grid(Ww / TW, Hh / TH, 16);       // 4 x 64 x 16 = 4096 blocks
    snn_fused14<<<grid, block, SMEM_BYTES>>>(tmap, conv_w, conv_b, gamma, beta_bn,
                                             run_mean, run_var, rho, out);
}